// round 13
// baseline (speedup 1.0000x reference)
#include <cuda_runtime.h>
#include <cuda_fp16.h>
#include <math.h>

#define NN 20000
#define EE 320000
#define NB 256
#define HIDC 64

// ---------------- scratch (device globals; no allocation) ----------------
__device__ float  g_h[(size_t)NN * 512];
__device__ __half g_zh[(size_t)NN * 512];
__device__ float  g_esp[(size_t)EE * 4];
__device__ int    g_srcp[EE];
__device__ float  g_ssrcA[NN * 4];
__device__ float  g_ssrcB[NN * 4];
__device__ float  g_sdstA[NN * 4];
__device__ float  g_sdstB[NN * 4];
__device__ float  g_cnt[NB];
__device__ float  g_psum[NB * 3];
__device__ int    g_deg[NN];
__device__ int    g_off[NN + 1];
__device__ int    g_cur[NN];
__device__ int    g_bsum[64];
__device__ float  g_gsum[NB * HIDC];

// ---------------- helpers ----------------
__device__ __forceinline__ float lrelu(float v) { return v > 0.f ? v : 0.2f * v; }
__device__ __forceinline__ float sigmoidf(float v) { return 1.f / (1.f + __expf(-v)); }

__device__ __forceinline__ void cvt8(uint4 p, float* f) {
    float2 t;
    t = __half22float2(*(__half2*)&p.x); f[0] = t.x; f[1] = t.y;
    t = __half22float2(*(__half2*)&p.y); f[2] = t.x; f[3] = t.y;
    t = __half22float2(*(__half2*)&p.z); f[4] = t.x; f[5] = t.y;
    t = __half22float2(*(__half2*)&p.w); f[6] = t.x; f[7] = t.y;
}

__device__ __forceinline__ void mvgate(float* x, float4 a, float4 b) {
    float gA = sigmoidf(a.x * x[0] + b.x);
    float nB = x[1] * x[1] + x[2] * x[2] + x[3] * x[3];
    float gB = sigmoidf(a.y * nB + b.y);
    float nC = x[4] * x[4] + x[5] * x[5] + x[6] * x[6];
    float gC = sigmoidf(a.z * nC + b.z);
    float gD = sigmoidf(a.w * x[7] * x[7] + b.w);
    x[0] *= gA; x[1] *= gB; x[2] *= gB; x[3] *= gB;
    x[4] *= gC; x[5] *= gC; x[6] *= gC; x[7] *= gD;
}

// ---------------- 0: zero scratch ----------------
__global__ void k_zero(int N) {
    int total = NB + NB * 3 + NB * HIDC + N;
    for (int i = blockIdx.x * blockDim.x + threadIdx.x; i < total; i += gridDim.x * blockDim.x) {
        if (i < NB) g_cnt[i] = 0.f;
        else if (i < NB + NB * 3) g_psum[i - NB] = 0.f;
        else if (i < NB + NB * 3 + NB * HIDC) g_gsum[i - NB - NB * 3] = 0.f;
        else g_deg[i - NB - NB * 3 - NB * HIDC] = 0;
    }
}

// ---------------- 1: batch stats + degree count ----------------
__global__ void k_init(const float* __restrict__ pos, const int* __restrict__ batch,
                       const int* __restrict__ dst, int N, int E) {
    int i = blockIdx.x * blockDim.x + threadIdx.x;
    if (i < N) {
        int b = batch[i];
        atomicAdd(&g_cnt[b], 1.f);
        atomicAdd(&g_psum[b * 3 + 0], pos[i * 3 + 0]);
        atomicAdd(&g_psum[b * 3 + 1], pos[i * 3 + 1]);
        atomicAdd(&g_psum[b * 3 + 2], pos[i * 3 + 2]);
    }
    if (i < E) atomicAdd(&g_deg[dst[i]], 1);
}

// ---------------- scan phase A ----------------
__global__ void __launch_bounds__(1024) k_scanA(int N) {
    __shared__ int swt[32];
    int t = threadIdx.x, b = blockIdx.x;
    int i = b * 1024 + t;
    int lane = t & 31, wid = t >> 5;
    int v = (i < N) ? g_deg[i] : 0;
    int x = v;
    #pragma unroll
    for (int o = 1; o < 32; o <<= 1) {
        int y = __shfl_up_sync(0xffffffffu, x, o);
        if (lane >= o) x += y;
    }
    if (lane == 31) swt[wid] = x;
    __syncthreads();
    if (t < 32) {
        int w = swt[t];
        #pragma unroll
        for (int o = 1; o < 32; o <<= 1) {
            int y = __shfl_up_sync(0xffffffffu, w, o);
            if (t >= o) w += y;
        }
        swt[t] = w;
    }
    __syncthreads();
    int base = (wid == 0) ? 0 : swt[wid - 1];
    if (i < N) g_off[i] = base + x - v;
    if (t == 1023) g_bsum[b] = base + x;
}

// ---------------- scan phase B ----------------
__global__ void __launch_bounds__(256) k_scanB(int N, int E, int G) {
    __shared__ int soff;
    int b = blockIdx.x, t = threadIdx.x;
    if (t == 0) {
        int s = 0;
        for (int j = 0; j < b; j++) s += g_bsum[j];
        soff = s;
        if (b == 0) g_off[N] = E;
    }
    __syncthreads();
    int s = soff;
    for (int k = t; k < 1024; k += 256) {
        int i = b * 1024 + k;
        if (i < N) {
            int val = g_off[i] + s;
            g_off[i] = val;
            g_cur[i] = val;
        }
    }
}

// ---------------- edge RBF-MLP + direct CSR scatter ----------------
__global__ void __launch_bounds__(128) k_edgefill(const float* __restrict__ pos,
        const int* __restrict__ src, const int* __restrict__ dst,
        const float* __restrict__ ew1, const float* __restrict__ eb1,
        const float* __restrict__ ew2, const float* __restrict__ eb2, int E) {
    __shared__ float s1[64 * 20];
    __shared__ float sb1[64];
    __shared__ float s2T[4 * 64];
    __shared__ float sb2v[4];
    int tid = threadIdx.x;
    for (int i = tid; i < 1280; i += 128) s1[i] = ew1[i];
    if (tid < 64) sb1[tid] = eb1[tid];
    for (int i = tid; i < 256; i += 128) {
        int o = i >> 2, h = i & 3;
        s2T[i] = ew2[h * 64 + o];
    }
    if (tid < 4) sb2v[tid] = eb2[tid];
    __syncthreads();
    int e = blockIdx.x * 128 + tid;
    if (e >= E) return;
    int s = src[e], d = dst[e];
    float dx = pos[s * 3] - pos[d * 3];
    float dy = pos[s * 3 + 1] - pos[d * 3 + 1];
    float dz = pos[s * 3 + 2] - pos[d * 3 + 2];
    float d2 = dx * dx + dy * dy + dz * dz;
    float dist = d2 > 0.f ? sqrtf(d2) : 0.f;
    const float width = 10.f / 19.f;
    const float invw = 19.f / 10.f;
    float rbf[20];
    #pragma unroll
    for (int k = 0; k < 20; k++) {
        float t = (dist - width * k) * invw;
        rbf[k] = __expf(-0.5f * t * t);
    }
    float a0 = 0.f, a1 = 0.f, a2 = 0.f, a3 = 0.f;
    #pragma unroll 2
    for (int o = 0; o < 64; o++) {
        float hv = sb1[o];
        const float4* w4 = (const float4*)&s1[o * 20];
        #pragma unroll
        for (int q = 0; q < 5; q++) {
            float4 w = w4[q];
            hv += w.x * rbf[q * 4] + w.y * rbf[q * 4 + 1] + w.z * rbf[q * 4 + 2] + w.w * rbf[q * 4 + 3];
        }
        float sv = hv * sigmoidf(hv);
        float4 w2 = ((const float4*)s2T)[o];
        a0 += w2.x * sv; a1 += w2.y * sv; a2 += w2.z * sv; a3 += w2.w * sv;
    }
    int p = atomicAdd(&g_cur[d], 1);
    g_srcp[p] = s;
    ((float4*)g_esp)[p] = make_float4(a0 + sb2v[0], a1 + sb2v[1], a2 + sb2v[2], a3 + sb2v[3]);
}

// ---------------- node embedding + input proj ----------------
__global__ void __launch_bounds__(256) k_embed(const int* __restrict__ zi,
        const int* __restrict__ batch, const float* __restrict__ pos,
        const float* __restrict__ atomw, const float* __restrict__ inw,
        const float* __restrict__ inb, int N) {
    __shared__ float wT[65 * 68];
    __shared__ float aT[64 * 36];
    __shared__ float sb[64];
    __shared__ float spx[32], spy[32], spz[32];
    __shared__ int   sz[32];
    int tid = threadIdx.x;
    int n0 = blockIdx.x * 32;

    if (tid < 32) {
        int n = n0 + tid;
        if (n < N) {
            int b = batch[n];
            float ic = 1.f / fmaxf(g_cnt[b], 1.f);
            spx[tid] = pos[n * 3 + 0] - g_psum[b * 3 + 0] * ic;
            spy[tid] = pos[n * 3 + 1] - g_psum[b * 3 + 1] * ic;
            spz[tid] = pos[n * 3 + 2] - g_psum[b * 3 + 2] * ic;
            sz[tid] = zi[n];
        } else { spx[tid] = spy[tid] = spz[tid] = 0.f; sz[tid] = 0; }
    }
    if (tid >= 32 && tid < 96) sb[tid - 32] = inb[tid - 32];
    for (int idx = tid; idx < 64 * 65; idx += 256) {
        int o = idx / 65, i = idx % 65;
        wT[i * 68 + o] = inw[idx];
    }
    __syncthreads();
    for (int idx = tid; idx < 64 * 32; idx += 256) {
        int n = idx & 31, i = idx >> 5;
        aT[i * 36 + n] = atomw[(size_t)sz[n] * 64 + i];
    }
    __syncthreads();

    int ox = (tid & 15) * 4;
    int nl = (tid >> 4) * 2;
    float acc[2][4];
    #pragma unroll
    for (int a = 0; a < 2; a++)
        #pragma unroll
        for (int b = 0; b < 4; b++) acc[a][b] = 0.f;

    #pragma unroll 8
    for (int i = 0; i < 64; i++) {
        float4 w = *(const float4*)&wT[i * 68 + ox];
        float2 a = *(const float2*)&aT[i * 36 + nl];
        acc[0][0] += a.x * w.x; acc[0][1] += a.x * w.y; acc[0][2] += a.x * w.z; acc[0][3] += a.x * w.w;
        acc[1][0] += a.y * w.x; acc[1][1] += a.y * w.y; acc[1][2] += a.y * w.z; acc[1][3] += a.y * w.w;
    }

    #pragma unroll
    for (int jj = 0; jj < 2; jj++) {
        int n = n0 + nl + jj;
        if (n >= N) break;
        float px = spx[nl + jj], py = spy[nl + jj], pz = spz[nl + jj];
        #pragma unroll
        for (int cc = 0; cc < 4; cc++) {
            int o = ox + cc;
            float vw = wT[64 * 68 + o];
            float4* hp = (float4*)(g_h + (size_t)n * 512 + o * 8);
            hp[0] = make_float4(acc[jj][cc] + sb[o], vw * px, vw * py, vw * pz);
            hp[1] = make_float4(0.f, 0.f, 0.f, 0.f);
        }
    }
}

// ---------------- per-grade MVLinear v4: fp16 W & X smem tiles ----------------
// grid (ceil(N/32), 2); blockIdx.y = half.
// W smem: [i][og] stride 136 halfs, 8 halfs = [g0 oo0..3][g1 oo0..3]
// X smem: [p][i] 8 halfs = [e0 b0..3][e1 b0..3]
__global__ void __launch_bounds__(256, 3) k_mvlin(const float* __restrict__ W,
        const float* __restrict__ B, const float* __restrict__ Asrc,
        const float* __restrict__ Adst, const float* __restrict__ Wsrc,
        const float* __restrict__ Wdst, int N) {
    extern __shared__ __half smh[];
    __half* Wsh = smh;            // 64 * 136 = 8704 halfs (17408 B)
    __half* Xsh = smh + 8704;     // 16 * 64 * 8 = 8192 halfs (16384 B)
    int tid = threadIdx.x;
    int half = blockIdx.y;
    int n0 = blockIdx.x * 32;
    const unsigned FULL = 0xffffffffu;

    const float* Wg = W + (size_t)(half * 2) * 4096;
    for (int idx = tid; idx < 4096; idx += 256) {
        int o = idx >> 6, i = idx & 63;
        int base = i * 136 + (o >> 2) * 8 + (o & 3);
        Wsh[base]     = __float2half(Wg[o * 64 + i]);
        Wsh[base + 4] = __float2half(Wg[4096 + o * 64 + i]);
    }
    for (int idx = tid; idx < 2048; idx += 256) {
        int j = idx >> 6, i4 = idx & 63;
        int n = n0 + j;
        float4 v = (n < N) ? ((const float4*)g_h)[(size_t)n * 128 + i4 * 2 + half]
                           : make_float4(0.f, 0.f, 0.f, 0.f);
        __half2 h01 = __floats2half2_rn(v.x, v.y);
        __half2 h23 = __floats2half2_rn(v.z, v.w);
        uint2 u;
        u.x = *(unsigned*)&h01;
        u.y = *(unsigned*)&h23;
        int p = j >> 1, e = j & 1;
        *(uint2*)&Xsh[((p * 64 + i4) * 8) + e * 4] = u;
    }
    __syncthreads();

    int og = tid & 15, ng = tid >> 4;
    int o0 = og * 4, nb = ng * 2;
    float acc[4][2][4];
    #pragma unroll
    for (int a = 0; a < 4; a++)
        #pragma unroll
        for (int b = 0; b < 2; b++)
            #pragma unroll
            for (int c = 0; c < 4; c++) acc[a][b][c] = 0.f;

    if (half == 0) {
        #pragma unroll 8
        for (int i = 0; i < 64; i++) {
            uint4 wv = *(const uint4*)&Wsh[i * 136 + og * 8];
            uint4 xv = *(const uint4*)&Xsh[(ng * 64 + i) * 8];
            float2 wa01 = __half22float2(*(__half2*)&wv.x);
            float2 wa23 = __half22float2(*(__half2*)&wv.y);
            float2 wb01 = __half22float2(*(__half2*)&wv.z);
            float2 wb23 = __half22float2(*(__half2*)&wv.w);
            float wA[4] = {wa01.x, wa01.y, wa23.x, wa23.y};
            float wB[4] = {wb01.x, wb01.y, wb23.x, wb23.y};
            float2 xa = __half22float2(*(__half2*)&xv.x);
            float2 xb = __half22float2(*(__half2*)&xv.y);
            float2 xc = __half22float2(*(__half2*)&xv.z);
            float2 xd = __half22float2(*(__half2*)&xv.w);
            float4 x0 = make_float4(xa.x, xa.y, xb.x, xb.y);
            float4 x1 = make_float4(xc.x, xc.y, xd.x, xd.y);
            #pragma unroll
            for (int oo = 0; oo < 4; oo++) {
                acc[oo][0][0] += wA[oo] * x0.x;
                acc[oo][0][1] += wB[oo] * x0.y;
                acc[oo][0][2] += wB[oo] * x0.z;
                acc[oo][0][3] += wB[oo] * x0.w;
                acc[oo][1][0] += wA[oo] * x1.x;
                acc[oo][1][1] += wB[oo] * x1.y;
                acc[oo][1][2] += wB[oo] * x1.z;
                acc[oo][1][3] += wB[oo] * x1.w;
            }
        }
    } else {
        #pragma unroll 8
        for (int i = 0; i < 64; i++) {
            uint4 wv = *(const uint4*)&Wsh[i * 136 + og * 8];
            uint4 xv = *(const uint4*)&Xsh[(ng * 64 + i) * 8];
            float2 wa01 = __half22float2(*(__half2*)&wv.x);
            float2 wa23 = __half22float2(*(__half2*)&wv.y);
            float2 wb01 = __half22float2(*(__half2*)&wv.z);
            float2 wb23 = __half22float2(*(__half2*)&wv.w);
            float wA[4] = {wa01.x, wa01.y, wa23.x, wa23.y};
            float wB[4] = {wb01.x, wb01.y, wb23.x, wb23.y};
            float2 xa = __half22float2(*(__half2*)&xv.x);
            float2 xb = __half22float2(*(__half2*)&xv.y);
            float2 xc = __half22float2(*(__half2*)&xv.z);
            float2 xd = __half22float2(*(__half2*)&xv.w);
            float4 x0 = make_float4(xa.x, xa.y, xb.x, xb.y);
            float4 x1 = make_float4(xc.x, xc.y, xd.x, xd.y);
            #pragma unroll
            for (int oo = 0; oo < 4; oo++) {
                acc[oo][0][0] += wA[oo] * x0.x;
                acc[oo][0][1] += wA[oo] * x0.y;
                acc[oo][0][2] += wA[oo] * x0.z;
                acc[oo][0][3] += wB[oo] * x0.w;
                acc[oo][1][0] += wA[oo] * x1.x;
                acc[oo][1][1] += wA[oo] * x1.y;
                acc[oo][1][2] += wA[oo] * x1.z;
                acc[oo][1][3] += wB[oo] * x1.w;
            }
        }
    }

    int head = og >> 2;
    float ws0, ws1, wd0, wd1;
    if (half == 0) { ws0 = Wsrc[head * 4 + 0]; ws1 = Wsrc[head * 4 + 1];
                     wd0 = Wdst[head * 4 + 0]; wd1 = Wdst[head * 4 + 1]; }
    else           { ws0 = Wsrc[head * 4 + 2]; ws1 = Wsrc[head * 4 + 3];
                     wd0 = Wdst[head * 4 + 2]; wd1 = Wdst[head * 4 + 3]; }

    #pragma unroll
    for (int jj = 0; jj < 2; jj++) {
        int n = n0 + nb + jj;
        bool ok = (n < N);
        float ps = 0.f, pd = 0.f;
        #pragma unroll
        for (int oo = 0; oo < 4; oo++) {
            int o = o0 + oo;
            float bb = (half == 0) ? B[o] : 0.f;
            float v0 = acc[oo][jj][0] + bb;
            float v1 = acc[oo][jj][1], v2 = acc[oo][jj][2], v3 = acc[oo][jj][3];
            if (ok) {
                __half2 ha = __floats2half2_rn(v0, v1);
                __half2 hb = __floats2half2_rn(v2, v3);
                uint2 u;
                u.x = *(unsigned*)&ha;
                u.y = *(unsigned*)&hb;
                *(uint2*)(g_zh + (size_t)n * 512 + o * 8 + half * 4) = u;
            }
            float4 Ab = *(const float4*)(Asrc + o * 8 + half * 4);
            float4 Db = *(const float4*)(Adst + o * 8 + half * 4);
            if (half == 0) {
                ps += v0 * Ab.x * ws0 + v1 * Ab.y * ws1 + v2 * Ab.z * ws1 + v3 * Ab.w * ws1;
                pd += v0 * Db.x * wd0 + v1 * Db.y * wd1 + v2 * Db.z * wd1 + v3 * Db.w * wd1;
            } else {
                ps += v0 * Ab.x * ws0 + v1 * Ab.y * ws0 + v2 * Ab.z * ws0 + v3 * Ab.w * ws1;
                pd += v0 * Db.x * wd0 + v1 * Db.y * wd0 + v2 * Db.z * wd0 + v3 * Db.w * wd1;
            }
        }
        ps += __shfl_xor_sync(FULL, ps, 1);
        ps += __shfl_xor_sync(FULL, ps, 2);
        pd += __shfl_xor_sync(FULL, pd, 1);
        pd += __shfl_xor_sync(FULL, pd, 2);
        if ((tid & 3) == 0 && ok) {
            if (half == 0) { g_ssrcA[n * 4 + head] = ps; g_sdstA[n * 4 + head] = pd; }
            else           { g_ssrcB[n * 4 + head] = ps; g_sdstB[n * 4 + head] = pd; }
        }
    }
}

// ---------------- warp-per-node attention (coalesced, depth-4, reads A+B partials) ----------------
__global__ void __launch_bounds__(128) k_attn(const float* __restrict__ sa,
        const float* __restrict__ sbp, const float* __restrict__ lna, int N) {
    __shared__ float4 salpha[4][64];
    __shared__ int    ssidx[4][64];
    int wslot = threadIdx.x >> 5;
    int n = blockIdx.x * 4 + wslot;
    int lane = threadIdx.x & 31;
    if (n >= N) return;
    int e0 = g_off[n];
    int deg = g_off[n + 1] - e0;
    float4 dA = ((const float4*)g_sdstA)[n];
    float4 dB = ((const float4*)g_sdstB)[n];
    float4 sd = make_float4(dA.x + dB.x, dA.y + dB.y, dA.z + dB.z, dA.w + dB.w);
    const unsigned FULL = 0xffffffffu;
    int hA = lane >> 4;

    bool fits = (deg <= 64);
    float4 mx = make_float4(-3e38f, -3e38f, -3e38f, -3e38f);

    if (fits) {
        #pragma unroll
        for (int r = 0; r < 2; r++) {
            int j = lane + r * 32;
            if (j < deg) {
                int s = g_srcp[e0 + j];
                float4 sA = ((const float4*)g_ssrcA)[s];
                float4 sB = ((const float4*)g_ssrcB)[s];
                float4 ev = ((const float4*)g_esp)[e0 + j];
                float4 lg = make_float4(lrelu(sA.x + sB.x + sd.x + ev.x),
                                        lrelu(sA.y + sB.y + sd.y + ev.y),
                                        lrelu(sA.z + sB.z + sd.z + ev.z),
                                        lrelu(sA.w + sB.w + sd.w + ev.w));
                salpha[wslot][j] = lg;
                ssidx[wslot][j] = s;
                mx.x = fmaxf(mx.x, lg.x); mx.y = fmaxf(mx.y, lg.y);
                mx.z = fmaxf(mx.z, lg.z); mx.w = fmaxf(mx.w, lg.w);
            }
        }
    } else {
        for (int j = lane; j < deg; j += 32) {
            int s = g_srcp[e0 + j];
            float4 sA = ((const float4*)g_ssrcA)[s];
            float4 sB = ((const float4*)g_ssrcB)[s];
            float4 ev = ((const float4*)g_esp)[e0 + j];
            mx.x = fmaxf(mx.x, lrelu(sA.x + sB.x + sd.x + ev.x));
            mx.y = fmaxf(mx.y, lrelu(sA.y + sB.y + sd.y + ev.y));
            mx.z = fmaxf(mx.z, lrelu(sA.z + sB.z + sd.z + ev.z));
            mx.w = fmaxf(mx.w, lrelu(sA.w + sB.w + sd.w + ev.w));
        }
    }
    #pragma unroll
    for (int off = 16; off; off >>= 1) {
        mx.x = fmaxf(mx.x, __shfl_xor_sync(FULL, mx.x, off));
        mx.y = fmaxf(mx.y, __shfl_xor_sync(FULL, mx.y, off));
        mx.z = fmaxf(mx.z, __shfl_xor_sync(FULL, mx.z, off));
        mx.w = fmaxf(mx.w, __shfl_xor_sync(FULL, mx.w, off));
    }

    float4 su = make_float4(0.f, 0.f, 0.f, 0.f);
    if (fits) {
        __syncwarp();
        #pragma unroll
        for (int r = 0; r < 2; r++) {
            int j = lane + r * 32;
            if (j < deg) {
                float4 lg = salpha[wslot][j];
                lg.x = __expf(lg.x - mx.x); lg.y = __expf(lg.y - mx.y);
                lg.z = __expf(lg.z - mx.z); lg.w = __expf(lg.w - mx.w);
                su.x += lg.x; su.y += lg.y; su.z += lg.z; su.w += lg.w;
                salpha[wslot][j] = lg;
            }
        }
        __syncwarp();
    } else {
        for (int j = lane; j < deg; j += 32) {
            int s = g_srcp[e0 + j];
            float4 sA = ((const float4*)g_ssrcA)[s];
            float4 sB = ((const float4*)g_ssrcB)[s];
            float4 ev = ((const float4*)g_esp)[e0 + j];
            su.x += __expf(lrelu(sA.x + sB.x + sd.x + ev.x) - mx.x);
            su.y += __expf(lrelu(sA.y + sB.y + sd.y + ev.y) - mx.y);
            su.z += __expf(lrelu(sA.z + sB.z + sd.z + ev.z) - mx.z);
            su.w += __expf(lrelu(sA.w + sB.w + sd.w + ev.w) - mx.w);
        }
    }
    #pragma unroll
    for (int off = 16; off; off >>= 1) {
        su.x += __shfl_xor_sync(FULL, su.x, off);
        su.y += __shfl_xor_sync(FULL, su.y, off);
        su.z += __shfl_xor_sync(FULL, su.z, off);
        su.w += __shfl_xor_sync(FULL, su.w, off);
    }

    float acc[16];
    #pragma unroll
    for (int k = 0; k < 16; k++) acc[k] = 0.f;

    if (fits) {
        const float* sal = (const float*)&salpha[wslot][0];
        const int* sidx = ssidx[wslot];
        int m = deg;
        uint4 A0, B0, A1, B1, A2, B2, A3, B3;
        float wa0 = 0.f, wb0 = 0.f, wa1 = 0.f, wb1 = 0.f;
        float wa2 = 0.f, wb2 = 0.f, wa3 = 0.f, wb3 = 0.f;
        if (0 < m) { int s = sidx[0]; wa0 = sal[hA];      wb0 = sal[2 + hA];
            const uint4* zp = (const uint4*)(g_zh + (size_t)s * 512); A0 = zp[lane]; B0 = zp[32 + lane]; }
        if (1 < m) { int s = sidx[1]; wa1 = sal[4 + hA];  wb1 = sal[6 + hA];
            const uint4* zp = (const uint4*)(g_zh + (size_t)s * 512); A1 = zp[lane]; B1 = zp[32 + lane]; }
        if (2 < m) { int s = sidx[2]; wa2 = sal[8 + hA];  wb2 = sal[10 + hA];
            const uint4* zp = (const uint4*)(g_zh + (size_t)s * 512); A2 = zp[lane]; B2 = zp[32 + lane]; }
        if (3 < m) { int s = sidx[3]; wa3 = sal[12 + hA]; wb3 = sal[14 + hA];
            const uint4* zp = (const uint4*)(g_zh + (size_t)s * 512); A3 = zp[lane]; B3 = zp[32 + lane]; }

        for (int l = 0; l < m; l += 4) {
            {
                uint4 cA = A0, cB = B0; float aa = wa0, ab = wb0;
                int lp = l + 4;
                if (lp < m) { int s = sidx[lp]; wa0 = sal[lp * 4 + hA]; wb0 = sal[lp * 4 + 2 + hA];
                    const uint4* zp = (const uint4*)(g_zh + (size_t)s * 512); A0 = zp[lane]; B0 = zp[32 + lane]; }
                float f[16]; cvt8(cA, f); cvt8(cB, f + 8);
                #pragma unroll
                for (int k = 0; k < 8; k++) acc[k] += aa * f[k];
                #pragma unroll
                for (int k = 8; k < 16; k++) acc[k] += ab * f[k];
            }
            if (l + 1 < m) {
                uint4 cA = A1, cB = B1; float aa = wa1, ab = wb1;
                int lp = l + 5;
                if (lp < m) { int s = sidx[lp]; wa1 = sal[lp * 4 + hA]; wb1 = sal[lp * 4 + 2 + hA];
                    const uint4* zp = (const uint4*)(g_zh + (size_t)s * 512); A1 = zp[lane]; B1 = zp[32 + lane]; }
                float f[16]; cvt8(cA, f); cvt8(cB, f + 8);
                #pragma unroll
                for (int k = 0; k < 8; k++) acc[k] += aa * f[k];
                #pragma unroll
                for (int k = 8; k < 16; k++) acc[k] += ab * f[k];
            }
            if (l + 2 < m) {
                uint4 cA = A2, cB = B2; float aa = wa2, ab = wb2;
                int lp = l + 6;
                if (lp < m) { int s = sidx[lp]; wa2 = sal[lp * 4 + hA]; wb2 = sal[lp * 4 + 2 + hA];
                    const uint4* zp = (const uint4*)(g_zh + (size_t)s * 512); A2 = zp[lane]; B2 = zp[32 + lane]; }
                float f[16]; cvt8(cA, f); cvt8(cB, f + 8);
                #pragma unroll
                for (int k = 0; k < 8; k++) acc[k] += aa * f[k];
                #pragma unroll
                for (int k = 8; k < 16; k++) acc[k] += ab * f[k];
            }
            if (l + 3 < m) {
                uint4 cA = A3, cB = B3; float aa = wa3, ab = wb3;
                int lp = l + 7;
                if (lp < m) { int s = sidx[lp]; wa3 = sal[lp * 4 + hA]; wb3 = sal[lp * 4 + 2 + hA];
                    const uint4* zp = (const uint4*)(g_zh + (size_t)s * 512); A3 = zp[lane]; B3 = zp[32 + lane]; }
                float f[16]; cvt8(cA, f); cvt8(cB, f + 8);
                #pragma unroll
                for (int k = 0; k < 8; k++) acc[k] += aa * f[k];
                #pragma unroll
                for (int k = 8; k < 16; k++) acc[k] += ab * f[k];
            }
        }
    } else {
        for (int j = 0; j < deg; j++) {
            int s = g_srcp[e0 + j];
            float4 sA = ((const float4*)g_ssrcA)[s];
            float4 sB = ((const float4*)g_ssrcB)[s];
            float4 ev = ((const float4*)g_esp)[e0 + j];
            float w0 = __expf(lrelu(sA.x + sB.x + sd.x + ev.x) - mx.x);
            float w1 = __expf(lrelu(sA.y + sB.y + sd.y + ev.y) - mx.y);
            float w2 = __expf(lrelu(sA.z + sB.z + sd.z + ev.z) - mx.z);
            float w3 = __expf(lrelu(sA.w + sB.w + sd.w + ev.w) - mx.w);
            float aa = hA == 0 ? w0 : w1;
            float ab = hA == 0 ? w2 : w3;
            const uint4* zp = (const uint4*)(g_zh + (size_t)s * 512);
            uint4 pA = zp[lane];
            uint4 pB = zp[32 + lane];
            float f[16];
            cvt8(pA, f);
            cvt8(pB, f + 8);
            #pragma unroll
            for (int k = 0; k < 8; k++) acc[k] += aa * f[k];
            #pragma unroll
            for (int k = 8; k < 16; k++) acc[k] += ab * f[k];
        }
    }

    float shA = hA == 0 ? su.x : su.y;
    float shB = hA == 0 ? su.z : su.w;
    float invA = 1.f / (shA + 1e-16f);
    float invB = 1.f / (shB + 1e-16f);
    float x[16];
    #pragma unroll
    for (int k = 0; k < 8; k++) x[k] = acc[k] * invA;
    #pragma unroll
    for (int k = 8; k < 16; k++) x[k] = acc[k] * invB;

    int c0 = lane, c1 = 32 + lane;
    float4 saA = ((const float4*)sa)[c0], sbA = ((const float4*)sbp)[c0];
    float4 saB = ((const float4*)sa)[c1], sbB = ((const float4*)sbp)[c1];
    mvgate(x, saA, sbA);
    mvgate(x + 8, saB, sbB);

    const float4* hr = (const float4*)(g_h + (size_t)n * 512);
    float4 r0 = hr[lane * 2], r1 = hr[lane * 2 + 1];
    float4 r2 = hr[64 + lane * 2], r3 = hr[64 + lane * 2 + 1];
    x[0] += r0.x;  x[1] += r0.y;  x[2] += r0.z;  x[3] += r0.w;
    x[4] += r1.x;  x[5] += r1.y;  x[6] += r1.z;  x[7] += r1.w;
    x[8] += r2.x;  x[9] += r2.y;  x[10] += r2.z; x[11] += r2.w;
    x[12] += r3.x; x[13] += r3.y; x[14] += r3.z; x[15] += r3.w;

    float ss0 = 0.f, ss1 = 0.f;
    #pragma unroll
    for (int k = 0; k < 8; k++) { ss0 += x[k] * x[k]; ss1 += x[8 + k] * x[8 + k]; }
    float cn = sqrtf(ss0) + sqrtf(ss1);
    #pragma unroll
    for (int off = 16; off; off >>= 1) cn += __shfl_xor_sync(FULL, cn, off);
    float mean = cn * (1.f / 64.f) + 1e-6f;
    float invm = 1.f / mean;
    float sc0 = lna[c0] * invm, sc1 = lna[c1] * invm;

    float4* hw = (float4*)(g_h + (size_t)n * 512);
    hw[lane * 2]     = make_float4(x[0] * sc0, x[1] * sc0, x[2] * sc0, x[3] * sc0);
    hw[lane * 2 + 1] = make_float4(x[4] * sc0, x[5] * sc0, x[6] * sc0, x[7] * sc0);
    hw[64 + lane * 2]     = make_float4(x[8] * sc1, x[9] * sc1, x[10] * sc1, x[11] * sc1);
    hw[64 + lane * 2 + 1] = make_float4(x[12] * sc1, x[13] * sc1, x[14] * sc1, x[15] * sc1);
}

// ---------------- prepool v2: tiled GEMM + atomic scatter ----------------
__global__ void __launch_bounds__(256) k_prepool(const float* __restrict__ ppw,
        const float* __restrict__ ppb, const int* __restrict__ batch, int N) {
    __shared__ float wT[64 * 68];
    __shared__ float xT[64 * 36];
    __shared__ float sb[64];
    __shared__ int   sbt[32];
    int tid = threadIdx.x;
    int n0 = blockIdx.x * 32;

    if (tid < 32) {
        int n = n0 + tid;
        sbt[tid] = (n < N) ? batch[n] : -1;
    }
    if (tid >= 64 && tid < 128) sb[tid - 64] = ppb[tid - 64];
    for (int idx = tid; idx < 4096; idx += 256) {
        int o = idx >> 6, i = idx & 63;
        wT[i * 68 + o] = ppw[idx];
    }
    for (int idx = tid; idx < 2048; idx += 256) {
        int n = idx & 31, i = idx >> 5;
        int nn = n0 + n;
        xT[i * 36 + n] = (nn < N) ? g_h[(size_t)nn * 512 + i * 8] : 0.f;
    }
    __syncthreads();

    int ox = (tid & 15) * 4;
    int nl = (tid >> 4) * 2;
    float acc[2][4];
    #pragma unroll
    for (int a = 0; a < 2; a++)
        #pragma unroll
        for (int b = 0; b < 4; b++) acc[a][b] = 0.f;

    #pragma unroll 8
    for (int i = 0; i < 64; i++) {
        float4 w = *(const float4*)&wT[i * 68 + ox];
        float2 a = *(const float2*)&xT[i * 36 + nl];
        acc[0][0] += a.x * w.x; acc[0][1] += a.x * w.y; acc[0][2] += a.x * w.z; acc[0][3] += a.x * w.w;
        acc[1][0] += a.y * w.x; acc[1][1] += a.y * w.y; acc[1][2] += a.y * w.z; acc[1][3] += a.y * w.w;
    }

    #pragma unroll
    for (int jj = 0; jj < 2; jj++) {
        int b = sbt[nl + jj];
        if (b < 0) continue;
        #pragma unroll
        for (int cc = 0; cc < 4; cc++) {
            int o = ox + cc;
            atomicAdd(&g_gsum[b * 64 + o], acc[jj][cc] + sb[o]);
        }
    }
}

__global__ void __launch_bounds__(64) k_post(const float* __restrict__ pw1,
        const float* __restrict__ pb1, const float* __restrict__ pw2,
        const float* __restrict__ pb2, float* __restrict__ out) {
    __shared__ float sg[64];
    __shared__ float sh[64];
    int b = blockIdx.x, tid = threadIdx.x;
    sg[tid] = g_gsum[b * 64 + tid];
    __syncthreads();
    float a = pb1[tid];
    const float* wr = pw1 + tid * 64;
    #pragma unroll 8
    for (int i = 0; i < 64; i++) a += wr[i] * sg[i];
    float s = a * sigmoidf(a);
    sh[tid] = s * pw2[tid];
    __syncthreads();
    for (int st = 32; st; st >>= 1) {
        if (tid < st) sh[tid] += sh[tid + st];
        __syncthreads();
    }
    if (tid == 0) out[b] = sh[0] + pb2[0];
}

// ---------------- launch ----------------
extern "C" void kernel_launch(void* const* d_in, const int* in_sizes, int n_in,
                              void* d_out, int out_size) {
    const float* pos   = (const float*)d_in[0];
    const int*   zi    = (const int*)d_in[1];
    const int*   ei    = (const int*)d_in[2];
    const int*   batch = (const int*)d_in[3];
    const float* atomw = (const float*)d_in[4];
    const float* inw   = (const float*)d_in[5];
    const float* inb   = (const float*)d_in[6];
    const float* ew1   = (const float*)d_in[7];
    const float* eb1   = (const float*)d_in[8];
    const float* ew2   = (const float*)d_in[9];
    const float* eb2   = (const float*)d_in[10];
    const float* projw = (const float*)d_in[11];
    const float* projb = (const float*)d_in[12];
    const float* asrc  = (const float*)d_in[13];
    const float* adst  = (const float*)d_in[14];
    const float* wsrc  = (const float*)d_in[15];
    const float* wdst  = (const float*)d_in[16];
    const float* lna   = (const float*)d_in[17];
    const float* silua = (const float*)d_in[18];
    const float* silub = (const float*)d_in[19];
    const float* ppw   = (const float*)d_in[20];
    const float* ppb   = (const float*)d_in[21];
    const float* pw1   = (const float*)d_in[22];
    const float* pb1   = (const float*)d_in[23];
    const float* pw2   = (const float*)d_in[24];
    const float* pb2   = (const float*)d_in[25];
    float* out = (float*)d_out;

    int N = in_sizes[0] / 3;
    int E = in_sizes[2] / 2;
    const int* src = ei;
    const int* dst = ei + E;
    int G = (N + 1023) / 1024;
    const int MVSMEM = (8704 + 8192) * 2;   // 33792 B (fp16 tiles)

    cudaFuncSetAttribute(k_mvlin, cudaFuncAttributeMaxDynamicSharedMemorySize, MVSMEM);

    k_zero<<<64, 256>>>(N);
    k_init<<<(E + 255) / 256, 256>>>(pos, batch, dst, N, E);
    k_embed<<<(N + 31) / 32, 256>>>(zi, batch, pos, atomw, inw, inb, N);
    dim3 mvgrid((N + 31) / 32, 2);
    k_mvlin<<<mvgrid, 256, MVSMEM>>>(projw, projb, asrc, adst, wsrc, wdst, N);
    k_scanA<<<G, 1024>>>(N);
    k_scanB<<<G, 256>>>(N, E, G);
    k_edgefill<<<(E + 127) / 128, 128>>>(pos, src, dst, ew1, eb1, ew2, eb2, E);

    k_attn<<<(N + 3) / 4, 128>>>(silua, silub, lna, N);
    for (int l = 1; l < 4; l++) {
        k_mvlin<<<mvgrid, 256, MVSMEM>>>(projw + (size_t)l * 4 * 64 * 64,
                                         projb + l * 64,
                                         asrc + l * 512, adst + l * 512,
                                         wsrc + l * 16, wdst + l * 16, N);
        k_attn<<<(N + 3) / 4, 128>>>(silua + l * 256, silub + l * 256, lna + l * 64, N);
    }

    k_prepool<<<(N + 31) / 32, 256>>>(ppw, ppb, batch, N);
    k_post<<<NB, 64>>>(pw1, pb1, pw2, pb2, out);
}

// round 14
// speedup vs baseline: 1.0947x; 1.0947x over previous
#include <cuda_runtime.h>
#include <cuda_fp16.h>
#include <math.h>

#define NN 20000
#define EE 320000
#define NB 256
#define HIDC 64

// ---------------- scratch (device globals; no allocation) ----------------
__device__ float  g_h[(size_t)NN * 512];
__device__ __half g_zh[(size_t)NN * 512];
__device__ float  g_esp[(size_t)EE * 4];
__device__ int    g_srcp[EE];
__device__ float  g_ssrcA[NN * 4];
__device__ float  g_ssrcB[NN * 4];
__device__ float  g_sdstA[NN * 4];
__device__ float  g_sdstB[NN * 4];
__device__ float  g_cnt[NB];
__device__ float  g_psum[NB * 3];
__device__ int    g_deg[NN];
__device__ int    g_off[NN + 1];
__device__ int    g_cur[NN];
__device__ int    g_bsum[64];
__device__ float  g_gsum[NB * HIDC];

// ---------------- helpers ----------------
__device__ __forceinline__ float lrelu(float v) { return v > 0.f ? v : 0.2f * v; }
__device__ __forceinline__ float sigmoidf(float v) { return 1.f / (1.f + __expf(-v)); }

__device__ __forceinline__ void cvt8(uint4 p, float* f) {
    float2 t;
    t = __half22float2(*(__half2*)&p.x); f[0] = t.x; f[1] = t.y;
    t = __half22float2(*(__half2*)&p.y); f[2] = t.x; f[3] = t.y;
    t = __half22float2(*(__half2*)&p.z); f[4] = t.x; f[5] = t.y;
    t = __half22float2(*(__half2*)&p.w); f[6] = t.x; f[7] = t.y;
}

__device__ __forceinline__ void mvgate(float* x, float4 a, float4 b) {
    float gA = sigmoidf(a.x * x[0] + b.x);
    float nB = x[1] * x[1] + x[2] * x[2] + x[3] * x[3];
    float gB = sigmoidf(a.y * nB + b.y);
    float nC = x[4] * x[4] + x[5] * x[5] + x[6] * x[6];
    float gC = sigmoidf(a.z * nC + b.z);
    float gD = sigmoidf(a.w * x[7] * x[7] + b.w);
    x[0] *= gA; x[1] *= gB; x[2] *= gB; x[3] *= gB;
    x[4] *= gC; x[5] *= gC; x[6] *= gC; x[7] *= gD;
}

// ---------------- 0: zero scratch ----------------
__global__ void k_zero(int N) {
    int total = NB + NB * 3 + NB * HIDC + N;
    for (int i = blockIdx.x * blockDim.x + threadIdx.x; i < total; i += gridDim.x * blockDim.x) {
        if (i < NB) g_cnt[i] = 0.f;
        else if (i < NB + NB * 3) g_psum[i - NB] = 0.f;
        else if (i < NB + NB * 3 + NB * HIDC) g_gsum[i - NB - NB * 3] = 0.f;
        else g_deg[i - NB - NB * 3 - NB * HIDC] = 0;
    }
}

// ---------------- 1: batch stats + degree count ----------------
__global__ void k_init(const float* __restrict__ pos, const int* __restrict__ batch,
                       const int* __restrict__ dst, int N, int E) {
    int i = blockIdx.x * blockDim.x + threadIdx.x;
    if (i < N) {
        int b = batch[i];
        atomicAdd(&g_cnt[b], 1.f);
        atomicAdd(&g_psum[b * 3 + 0], pos[i * 3 + 0]);
        atomicAdd(&g_psum[b * 3 + 1], pos[i * 3 + 1]);
        atomicAdd(&g_psum[b * 3 + 2], pos[i * 3 + 2]);
    }
    if (i < E) atomicAdd(&g_deg[dst[i]], 1);
}

// ---------------- scan phase A ----------------
__global__ void __launch_bounds__(1024) k_scanA(int N) {
    __shared__ int swt[32];
    int t = threadIdx.x, b = blockIdx.x;
    int i = b * 1024 + t;
    int lane = t & 31, wid = t >> 5;
    int v = (i < N) ? g_deg[i] : 0;
    int x = v;
    #pragma unroll
    for (int o = 1; o < 32; o <<= 1) {
        int y = __shfl_up_sync(0xffffffffu, x, o);
        if (lane >= o) x += y;
    }
    if (lane == 31) swt[wid] = x;
    __syncthreads();
    if (t < 32) {
        int w = swt[t];
        #pragma unroll
        for (int o = 1; o < 32; o <<= 1) {
            int y = __shfl_up_sync(0xffffffffu, w, o);
            if (t >= o) w += y;
        }
        swt[t] = w;
    }
    __syncthreads();
    int base = (wid == 0) ? 0 : swt[wid - 1];
    if (i < N) g_off[i] = base + x - v;
    if (t == 1023) g_bsum[b] = base + x;
}

// ---------------- scan phase B ----------------
__global__ void __launch_bounds__(256) k_scanB(int N, int E, int G) {
    __shared__ int soff;
    int b = blockIdx.x, t = threadIdx.x;
    if (t == 0) {
        int s = 0;
        for (int j = 0; j < b; j++) s += g_bsum[j];
        soff = s;
        if (b == 0) g_off[N] = E;
    }
    __syncthreads();
    int s = soff;
    for (int k = t; k < 1024; k += 256) {
        int i = b * 1024 + k;
        if (i < N) {
            int val = g_off[i] + s;
            g_off[i] = val;
            g_cur[i] = val;
        }
    }
}

// ---------------- edge RBF-MLP + direct CSR scatter ----------------
__global__ void __launch_bounds__(128) k_edgefill(const float* __restrict__ pos,
        const int* __restrict__ src, const int* __restrict__ dst,
        const float* __restrict__ ew1, const float* __restrict__ eb1,
        const float* __restrict__ ew2, const float* __restrict__ eb2, int E) {
    __shared__ float s1[64 * 20];
    __shared__ float sb1[64];
    __shared__ float s2T[4 * 64];
    __shared__ float sb2v[4];
    int tid = threadIdx.x;
    for (int i = tid; i < 1280; i += 128) s1[i] = ew1[i];
    if (tid < 64) sb1[tid] = eb1[tid];
    for (int i = tid; i < 256; i += 128) {
        int o = i >> 2, h = i & 3;
        s2T[i] = ew2[h * 64 + o];
    }
    if (tid < 4) sb2v[tid] = eb2[tid];
    __syncthreads();
    int e = blockIdx.x * 128 + tid;
    if (e >= E) return;
    int s = src[e], d = dst[e];
    float dx = pos[s * 3] - pos[d * 3];
    float dy = pos[s * 3 + 1] - pos[d * 3 + 1];
    float dz = pos[s * 3 + 2] - pos[d * 3 + 2];
    float d2 = dx * dx + dy * dy + dz * dz;
    float dist = d2 > 0.f ? sqrtf(d2) : 0.f;
    const float width = 10.f / 19.f;
    const float invw = 19.f / 10.f;
    float rbf[20];
    #pragma unroll
    for (int k = 0; k < 20; k++) {
        float t = (dist - width * k) * invw;
        rbf[k] = __expf(-0.5f * t * t);
    }
    float a0 = 0.f, a1 = 0.f, a2 = 0.f, a3 = 0.f;
    #pragma unroll 2
    for (int o = 0; o < 64; o++) {
        float hv = sb1[o];
        const float4* w4 = (const float4*)&s1[o * 20];
        #pragma unroll
        for (int q = 0; q < 5; q++) {
            float4 w = w4[q];
            hv += w.x * rbf[q * 4] + w.y * rbf[q * 4 + 1] + w.z * rbf[q * 4 + 2] + w.w * rbf[q * 4 + 3];
        }
        float sv = hv * sigmoidf(hv);
        float4 w2 = ((const float4*)s2T)[o];
        a0 += w2.x * sv; a1 += w2.y * sv; a2 += w2.z * sv; a3 += w2.w * sv;
    }
    int p = atomicAdd(&g_cur[d], 1);
    g_srcp[p] = s;
    ((float4*)g_esp)[p] = make_float4(a0 + sb2v[0], a1 + sb2v[1], a2 + sb2v[2], a3 + sb2v[3]);
}

// ---------------- node embedding + input proj ----------------
__global__ void __launch_bounds__(256) k_embed(const int* __restrict__ zi,
        const int* __restrict__ batch, const float* __restrict__ pos,
        const float* __restrict__ atomw, const float* __restrict__ inw,
        const float* __restrict__ inb, int N) {
    __shared__ float wT[65 * 68];
    __shared__ float aT[64 * 36];
    __shared__ float sb[64];
    __shared__ float spx[32], spy[32], spz[32];
    __shared__ int   sz[32];
    int tid = threadIdx.x;
    int n0 = blockIdx.x * 32;

    if (tid < 32) {
        int n = n0 + tid;
        if (n < N) {
            int b = batch[n];
            float ic = 1.f / fmaxf(g_cnt[b], 1.f);
            spx[tid] = pos[n * 3 + 0] - g_psum[b * 3 + 0] * ic;
            spy[tid] = pos[n * 3 + 1] - g_psum[b * 3 + 1] * ic;
            spz[tid] = pos[n * 3 + 2] - g_psum[b * 3 + 2] * ic;
            sz[tid] = zi[n];
        } else { spx[tid] = spy[tid] = spz[tid] = 0.f; sz[tid] = 0; }
    }
    if (tid >= 32 && tid < 96) sb[tid - 32] = inb[tid - 32];
    for (int idx = tid; idx < 64 * 65; idx += 256) {
        int o = idx / 65, i = idx % 65;
        wT[i * 68 + o] = inw[idx];
    }
    __syncthreads();
    for (int idx = tid; idx < 64 * 32; idx += 256) {
        int n = idx & 31, i = idx >> 5;
        aT[i * 36 + n] = atomw[(size_t)sz[n] * 64 + i];
    }
    __syncthreads();

    int ox = (tid & 15) * 4;
    int nl = (tid >> 4) * 2;
    float acc[2][4];
    #pragma unroll
    for (int a = 0; a < 2; a++)
        #pragma unroll
        for (int b = 0; b < 4; b++) acc[a][b] = 0.f;

    #pragma unroll 8
    for (int i = 0; i < 64; i++) {
        float4 w = *(const float4*)&wT[i * 68 + ox];
        float2 a = *(const float2*)&aT[i * 36 + nl];
        acc[0][0] += a.x * w.x; acc[0][1] += a.x * w.y; acc[0][2] += a.x * w.z; acc[0][3] += a.x * w.w;
        acc[1][0] += a.y * w.x; acc[1][1] += a.y * w.y; acc[1][2] += a.y * w.z; acc[1][3] += a.y * w.w;
    }

    #pragma unroll
    for (int jj = 0; jj < 2; jj++) {
        int n = n0 + nl + jj;
        if (n >= N) break;
        float px = spx[nl + jj], py = spy[nl + jj], pz = spz[nl + jj];
        #pragma unroll
        for (int cc = 0; cc < 4; cc++) {
            int o = ox + cc;
            float vw = wT[64 * 68 + o];
            float4* hp = (float4*)(g_h + (size_t)n * 512 + o * 8);
            hp[0] = make_float4(acc[jj][cc] + sb[o], vw * px, vw * py, vw * pz);
            hp[1] = make_float4(0.f, 0.f, 0.f, 0.f);
        }
    }
}

// ---------------- per-grade MVLinear v3 (fp32, unroll 8 — R11 config) ----------------
__global__ void __launch_bounds__(256, 3) k_mvlin(const float* __restrict__ W,
        const float* __restrict__ B, const float* __restrict__ Asrc,
        const float* __restrict__ Adst, const float* __restrict__ Wsrc,
        const float* __restrict__ Wdst, int N) {
    extern __shared__ float sm[];
    float* WsT = sm;
    float* Xs  = sm + 8704;
    int tid = threadIdx.x;
    int half = blockIdx.y;
    int n0 = blockIdx.x * 32;
    const unsigned FULL = 0xffffffffu;

    const float* Wg = W + (size_t)(half * 2) * 4096;
    for (int idx = tid; idx < 4096; idx += 256) {
        int o = idx >> 6, i = idx & 63;
        WsT[i * 68 + o]        = Wg[o * 64 + i];
        WsT[4352 + i * 68 + o] = Wg[4096 + o * 64 + i];
    }
    for (int idx = tid; idx < 2048; idx += 256) {
        int j = idx >> 6, i4 = idx & 63;
        int n = n0 + j;
        float4 v = (n < N) ? ((const float4*)g_h)[(size_t)n * 128 + i4 * 2 + half]
                           : make_float4(0.f, 0.f, 0.f, 0.f);
        *(float4*)&Xs[j * 256 + i4 * 4] = v;
    }
    __syncthreads();

    int og = tid & 15, ng = tid >> 4;
    int o0 = og * 4, nb = ng * 2;
    float acc[4][2][4];
    #pragma unroll
    for (int a = 0; a < 4; a++)
        #pragma unroll
        for (int b = 0; b < 2; b++)
            #pragma unroll
            for (int c = 0; c < 4; c++) acc[a][b][c] = 0.f;

    if (half == 0) {
        #pragma unroll 8
        for (int i = 0; i < 64; i++) {
            float4 wa = *(const float4*)&WsT[i * 68 + o0];
            float4 wb = *(const float4*)&WsT[4352 + i * 68 + o0];
            float4 x0 = *(const float4*)&Xs[nb * 256 + i * 4];
            float4 x1 = *(const float4*)&Xs[(nb + 1) * 256 + i * 4];
            float wA[4] = {wa.x, wa.y, wa.z, wa.w};
            float wB[4] = {wb.x, wb.y, wb.z, wb.w};
            #pragma unroll
            for (int oo = 0; oo < 4; oo++) {
                acc[oo][0][0] += wA[oo] * x0.x;
                acc[oo][0][1] += wB[oo] * x0.y;
                acc[oo][0][2] += wB[oo] * x0.z;
                acc[oo][0][3] += wB[oo] * x0.w;
                acc[oo][1][0] += wA[oo] * x1.x;
                acc[oo][1][1] += wB[oo] * x1.y;
                acc[oo][1][2] += wB[oo] * x1.z;
                acc[oo][1][3] += wB[oo] * x1.w;
            }
        }
    } else {
        #pragma unroll 8
        for (int i = 0; i < 64; i++) {
            float4 wa = *(const float4*)&WsT[i * 68 + o0];
            float4 wb = *(const float4*)&WsT[4352 + i * 68 + o0];
            float4 x0 = *(const float4*)&Xs[nb * 256 + i * 4];
            float4 x1 = *(const float4*)&Xs[(nb + 1) * 256 + i * 4];
            float wA[4] = {wa.x, wa.y, wa.z, wa.w};
            float wB[4] = {wb.x, wb.y, wb.z, wb.w};
            #pragma unroll
            for (int oo = 0; oo < 4; oo++) {
                acc[oo][0][0] += wA[oo] * x0.x;
                acc[oo][0][1] += wA[oo] * x0.y;
                acc[oo][0][2] += wA[oo] * x0.z;
                acc[oo][0][3] += wB[oo] * x0.w;
                acc[oo][1][0] += wA[oo] * x1.x;
                acc[oo][1][1] += wA[oo] * x1.y;
                acc[oo][1][2] += wA[oo] * x1.z;
                acc[oo][1][3] += wB[oo] * x1.w;
            }
        }
    }

    int head = og >> 2;
    float ws0, ws1, wd0, wd1;
    if (half == 0) { ws0 = Wsrc[head * 4 + 0]; ws1 = Wsrc[head * 4 + 1];
                     wd0 = Wdst[head * 4 + 0]; wd1 = Wdst[head * 4 + 1]; }
    else           { ws0 = Wsrc[head * 4 + 2]; ws1 = Wsrc[head * 4 + 3];
                     wd0 = Wdst[head * 4 + 2]; wd1 = Wdst[head * 4 + 3]; }

    #pragma unroll
    for (int jj = 0; jj < 2; jj++) {
        int n = n0 + nb + jj;
        bool ok = (n < N);
        float ps = 0.f, pd = 0.f;
        #pragma unroll
        for (int oo = 0; oo < 4; oo++) {
            int o = o0 + oo;
            float bb = (half == 0) ? B[o] : 0.f;
            float v0 = acc[oo][jj][0] + bb;
            float v1 = acc[oo][jj][1], v2 = acc[oo][jj][2], v3 = acc[oo][jj][3];
            if (ok) {
                __half2 ha = __floats2half2_rn(v0, v1);
                __half2 hb = __floats2half2_rn(v2, v3);
                uint2 u;
                u.x = *(unsigned*)&ha;
                u.y = *(unsigned*)&hb;
                *(uint2*)(g_zh + (size_t)n * 512 + o * 8 + half * 4) = u;
            }
            float4 Ab = *(const float4*)(Asrc + o * 8 + half * 4);
            float4 Db = *(const float4*)(Adst + o * 8 + half * 4);
            if (half == 0) {
                ps += v0 * Ab.x * ws0 + v1 * Ab.y * ws1 + v2 * Ab.z * ws1 + v3 * Ab.w * ws1;
                pd += v0 * Db.x * wd0 + v1 * Db.y * wd1 + v2 * Db.z * wd1 + v3 * Db.w * wd1;
            } else {
                ps += v0 * Ab.x * ws0 + v1 * Ab.y * ws0 + v2 * Ab.z * ws0 + v3 * Ab.w * ws1;
                pd += v0 * Db.x * wd0 + v1 * Db.y * wd0 + v2 * Db.z * wd0 + v3 * Db.w * wd1;
            }
        }
        ps += __shfl_xor_sync(FULL, ps, 1);
        ps += __shfl_xor_sync(FULL, ps, 2);
        pd += __shfl_xor_sync(FULL, pd, 1);
        pd += __shfl_xor_sync(FULL, pd, 2);
        if ((tid & 3) == 0 && ok) {
            if (half == 0) { g_ssrcA[n * 4 + head] = ps; g_sdstA[n * 4 + head] = pd; }
            else           { g_ssrcB[n * 4 + head] = ps; g_sdstB[n * 4 + head] = pd; }
        }
    }
}

// ---------------- warp-per-node attention (coalesced, depth-4, reads A+B partials) ----------------
__global__ void __launch_bounds__(128) k_attn(const float* __restrict__ sa,
        const float* __restrict__ sbp, const float* __restrict__ lna, int N) {
    __shared__ float4 salpha[4][64];
    __shared__ int    ssidx[4][64];
    int wslot = threadIdx.x >> 5;
    int n = blockIdx.x * 4 + wslot;
    int lane = threadIdx.x & 31;
    if (n >= N) return;
    int e0 = g_off[n];
    int deg = g_off[n + 1] - e0;
    float4 dA = ((const float4*)g_sdstA)[n];
    float4 dB = ((const float4*)g_sdstB)[n];
    float4 sd = make_float4(dA.x + dB.x, dA.y + dB.y, dA.z + dB.z, dA.w + dB.w);
    const unsigned FULL = 0xffffffffu;
    int hA = lane >> 4;

    bool fits = (deg <= 64);
    float4 mx = make_float4(-3e38f, -3e38f, -3e38f, -3e38f);

    if (fits) {
        #pragma unroll
        for (int r = 0; r < 2; r++) {
            int j = lane + r * 32;
            if (j < deg) {
                int s = g_srcp[e0 + j];
                float4 sA = ((const float4*)g_ssrcA)[s];
                float4 sB = ((const float4*)g_ssrcB)[s];
                float4 ev = ((const float4*)g_esp)[e0 + j];
                float4 lg = make_float4(lrelu(sA.x + sB.x + sd.x + ev.x),
                                        lrelu(sA.y + sB.y + sd.y + ev.y),
                                        lrelu(sA.z + sB.z + sd.z + ev.z),
                                        lrelu(sA.w + sB.w + sd.w + ev.w));
                salpha[wslot][j] = lg;
                ssidx[wslot][j] = s;
                mx.x = fmaxf(mx.x, lg.x); mx.y = fmaxf(mx.y, lg.y);
                mx.z = fmaxf(mx.z, lg.z); mx.w = fmaxf(mx.w, lg.w);
            }
        }
    } else {
        for (int j = lane; j < deg; j += 32) {
            int s = g_srcp[e0 + j];
            float4 sA = ((const float4*)g_ssrcA)[s];
            float4 sB = ((const float4*)g_ssrcB)[s];
            float4 ev = ((const float4*)g_esp)[e0 + j];
            mx.x = fmaxf(mx.x, lrelu(sA.x + sB.x + sd.x + ev.x));
            mx.y = fmaxf(mx.y, lrelu(sA.y + sB.y + sd.y + ev.y));
            mx.z = fmaxf(mx.z, lrelu(sA.z + sB.z + sd.z + ev.z));
            mx.w = fmaxf(mx.w, lrelu(sA.w + sB.w + sd.w + ev.w));
        }
    }
    #pragma unroll
    for (int off = 16; off; off >>= 1) {
        mx.x = fmaxf(mx.x, __shfl_xor_sync(FULL, mx.x, off));
        mx.y = fmaxf(mx.y, __shfl_xor_sync(FULL, mx.y, off));
        mx.z = fmaxf(mx.z, __shfl_xor_sync(FULL, mx.z, off));
        mx.w = fmaxf(mx.w, __shfl_xor_sync(FULL, mx.w, off));
    }

    float4 su = make_float4(0.f, 0.f, 0.f, 0.f);
    if (fits) {
        __syncwarp();
        #pragma unroll
        for (int r = 0; r < 2; r++) {
            int j = lane + r * 32;
            if (j < deg) {
                float4 lg = salpha[wslot][j];
                lg.x = __expf(lg.x - mx.x); lg.y = __expf(lg.y - mx.y);
                lg.z = __expf(lg.z - mx.z); lg.w = __expf(lg.w - mx.w);
                su.x += lg.x; su.y += lg.y; su.z += lg.z; su.w += lg.w;
                salpha[wslot][j] = lg;
            }
        }
        __syncwarp();
    } else {
        for (int j = lane; j < deg; j += 32) {
            int s = g_srcp[e0 + j];
            float4 sA = ((const float4*)g_ssrcA)[s];
            float4 sB = ((const float4*)g_ssrcB)[s];
            float4 ev = ((const float4*)g_esp)[e0 + j];
            su.x += __expf(lrelu(sA.x + sB.x + sd.x + ev.x) - mx.x);
            su.y += __expf(lrelu(sA.y + sB.y + sd.y + ev.y) - mx.y);
            su.z += __expf(lrelu(sA.z + sB.z + sd.z + ev.z) - mx.z);
            su.w += __expf(lrelu(sA.w + sB.w + sd.w + ev.w) - mx.w);
        }
    }
    #pragma unroll
    for (int off = 16; off; off >>= 1) {
        su.x += __shfl_xor_sync(FULL, su.x, off);
        su.y += __shfl_xor_sync(FULL, su.y, off);
        su.z += __shfl_xor_sync(FULL, su.z, off);
        su.w += __shfl_xor_sync(FULL, su.w, off);
    }

    float acc[16];
    #pragma unroll
    for (int k = 0; k < 16; k++) acc[k] = 0.f;

    if (fits) {
        const float* sal = (const float*)&salpha[wslot][0];
        const int* sidx = ssidx[wslot];
        int m = deg;
        uint4 A0, B0, A1, B1, A2, B2, A3, B3;
        float wa0 = 0.f, wb0 = 0.f, wa1 = 0.f, wb1 = 0.f;
        float wa2 = 0.f, wb2 = 0.f, wa3 = 0.f, wb3 = 0.f;
        if (0 < m) { int s = sidx[0]; wa0 = sal[hA];      wb0 = sal[2 + hA];
            const uint4* zp = (const uint4*)(g_zh + (size_t)s * 512); A0 = zp[lane]; B0 = zp[32 + lane]; }
        if (1 < m) { int s = sidx[1]; wa1 = sal[4 + hA];  wb1 = sal[6 + hA];
            const uint4* zp = (const uint4*)(g_zh + (size_t)s * 512); A1 = zp[lane]; B1 = zp[32 + lane]; }
        if (2 < m) { int s = sidx[2]; wa2 = sal[8 + hA];  wb2 = sal[10 + hA];
            const uint4* zp = (const uint4*)(g_zh + (size_t)s * 512); A2 = zp[lane]; B2 = zp[32 + lane]; }
        if (3 < m) { int s = sidx[3]; wa3 = sal[12 + hA]; wb3 = sal[14 + hA];
            const uint4* zp = (const uint4*)(g_zh + (size_t)s * 512); A3 = zp[lane]; B3 = zp[32 + lane]; }

        for (int l = 0; l < m; l += 4) {
            {
                uint4 cA = A0, cB = B0; float aa = wa0, ab = wb0;
                int lp = l + 4;
                if (lp < m) { int s = sidx[lp]; wa0 = sal[lp * 4 + hA]; wb0 = sal[lp * 4 + 2 + hA];
                    const uint4* zp = (const uint4*)(g_zh + (size_t)s * 512); A0 = zp[lane]; B0 = zp[32 + lane]; }
                float f[16]; cvt8(cA, f); cvt8(cB, f + 8);
                #pragma unroll
                for (int k = 0; k < 8; k++) acc[k] += aa * f[k];
                #pragma unroll
                for (int k = 8; k < 16; k++) acc[k] += ab * f[k];
            }
            if (l + 1 < m) {
                uint4 cA = A1, cB = B1; float aa = wa1, ab = wb1;
                int lp = l + 5;
                if (lp < m) { int s = sidx[lp]; wa1 = sal[lp * 4 + hA]; wb1 = sal[lp * 4 + 2 + hA];
                    const uint4* zp = (const uint4*)(g_zh + (size_t)s * 512); A1 = zp[lane]; B1 = zp[32 + lane]; }
                float f[16]; cvt8(cA, f); cvt8(cB, f + 8);
                #pragma unroll
                for (int k = 0; k < 8; k++) acc[k] += aa * f[k];
                #pragma unroll
                for (int k = 8; k < 16; k++) acc[k] += ab * f[k];
            }
            if (l + 2 < m) {
                uint4 cA = A2, cB = B2; float aa = wa2, ab = wb2;
                int lp = l + 6;
                if (lp < m) { int s = sidx[lp]; wa2 = sal[lp * 4 + hA]; wb2 = sal[lp * 4 + 2 + hA];
                    const uint4* zp = (const uint4*)(g_zh + (size_t)s * 512); A2 = zp[lane]; B2 = zp[32 + lane]; }
                float f[16]; cvt8(cA, f); cvt8(cB, f + 8);
                #pragma unroll
                for (int k = 0; k < 8; k++) acc[k] += aa * f[k];
                #pragma unroll
                for (int k = 8; k < 16; k++) acc[k] += ab * f[k];
            }
            if (l + 3 < m) {
                uint4 cA = A3, cB = B3; float aa = wa3, ab = wb3;
                int lp = l + 7;
                if (lp < m) { int s = sidx[lp]; wa3 = sal[lp * 4 + hA]; wb3 = sal[lp * 4 + 2 + hA];
                    const uint4* zp = (const uint4*)(g_zh + (size_t)s * 512); A3 = zp[lane]; B3 = zp[32 + lane]; }
                float f[16]; cvt8(cA, f); cvt8(cB, f + 8);
                #pragma unroll
                for (int k = 0; k < 8; k++) acc[k] += aa * f[k];
                #pragma unroll
                for (int k = 8; k < 16; k++) acc[k] += ab * f[k];
            }
        }
    } else {
        for (int j = 0; j < deg; j++) {
            int s = g_srcp[e0 + j];
            float4 sA = ((const float4*)g_ssrcA)[s];
            float4 sB = ((const float4*)g_ssrcB)[s];
            float4 ev = ((const float4*)g_esp)[e0 + j];
            float w0 = __expf(lrelu(sA.x + sB.x + sd.x + ev.x) - mx.x);
            float w1 = __expf(lrelu(sA.y + sB.y + sd.y + ev.y) - mx.y);
            float w2 = __expf(lrelu(sA.z + sB.z + sd.z + ev.z) - mx.z);
            float w3 = __expf(lrelu(sA.w + sB.w + sd.w + ev.w) - mx.w);
            float aa = hA == 0 ? w0 : w1;
            float ab = hA == 0 ? w2 : w3;
            const uint4* zp = (const uint4*)(g_zh + (size_t)s * 512);
            uint4 pA = zp[lane];
            uint4 pB = zp[32 + lane];
            float f[16];
            cvt8(pA, f);
            cvt8(pB, f + 8);
            #pragma unroll
            for (int k = 0; k < 8; k++) acc[k] += aa * f[k];
            #pragma unroll
            for (int k = 8; k < 16; k++) acc[k] += ab * f[k];
        }
    }

    float shA = hA == 0 ? su.x : su.y;
    float shB = hA == 0 ? su.z : su.w;
    float invA = 1.f / (shA + 1e-16f);
    float invB = 1.f / (shB + 1e-16f);
    float x[16];
    #pragma unroll
    for (int k = 0; k < 8; k++) x[k] = acc[k] * invA;
    #pragma unroll
    for (int k = 8; k < 16; k++) x[k] = acc[k] * invB;

    int c0 = lane, c1 = 32 + lane;
    float4 saA = ((const float4*)sa)[c0], sbA = ((const float4*)sbp)[c0];
    float4 saB = ((const float4*)sa)[c1], sbB = ((const float4*)sbp)[c1];
    mvgate(x, saA, sbA);
    mvgate(x + 8, saB, sbB);

    const float4* hr = (const float4*)(g_h + (size_t)n * 512);
    float4 r0 = hr[lane * 2], r1 = hr[lane * 2 + 1];
    float4 r2 = hr[64 + lane * 2], r3 = hr[64 + lane * 2 + 1];
    x[0] += r0.x;  x[1] += r0.y;  x[2] += r0.z;  x[3] += r0.w;
    x[4] += r1.x;  x[5] += r1.y;  x[6] += r1.z;  x[7] += r1.w;
    x[8] += r2.x;  x[9] += r2.y;  x[10] += r2.z; x[11] += r2.w;
    x[12] += r3.x; x[13] += r3.y; x[14] += r3.z; x[15] += r3.w;

    float ss0 = 0.f, ss1 = 0.f;
    #pragma unroll
    for (int k = 0; k < 8; k++) { ss0 += x[k] * x[k]; ss1 += x[8 + k] * x[8 + k]; }
    float cn = sqrtf(ss0) + sqrtf(ss1);
    #pragma unroll
    for (int off = 16; off; off >>= 1) cn += __shfl_xor_sync(FULL, cn, off);
    float mean = cn * (1.f / 64.f) + 1e-6f;
    float invm = 1.f / mean;
    float sc0 = lna[c0] * invm, sc1 = lna[c1] * invm;

    float4* hw = (float4*)(g_h + (size_t)n * 512);
    hw[lane * 2]     = make_float4(x[0] * sc0, x[1] * sc0, x[2] * sc0, x[3] * sc0);
    hw[lane * 2 + 1] = make_float4(x[4] * sc0, x[5] * sc0, x[6] * sc0, x[7] * sc0);
    hw[64 + lane * 2]     = make_float4(x[8] * sc1, x[9] * sc1, x[10] * sc1, x[11] * sc1);
    hw[64 + lane * 2 + 1] = make_float4(x[12] * sc1, x[13] * sc1, x[14] * sc1, x[15] * sc1);
}

// ---------------- prepool v2: tiled GEMM + atomic scatter ----------------
__global__ void __launch_bounds__(256) k_prepool(const float* __restrict__ ppw,
        const float* __restrict__ ppb, const int* __restrict__ batch, int N) {
    __shared__ float wT[64 * 68];
    __shared__ float xT[64 * 36];
    __shared__ float sb[64];
    __shared__ int   sbt[32];
    int tid = threadIdx.x;
    int n0 = blockIdx.x * 32;

    if (tid < 32) {
        int n = n0 + tid;
        sbt[tid] = (n < N) ? batch[n] : -1;
    }
    if (tid >= 64 && tid < 128) sb[tid - 64] = ppb[tid - 64];
    for (int idx = tid; idx < 4096; idx += 256) {
        int o = idx >> 6, i = idx & 63;
        wT[i * 68 + o] = ppw[idx];
    }
    for (int idx = tid; idx < 2048; idx += 256) {
        int n = idx & 31, i = idx >> 5;
        int nn = n0 + n;
        xT[i * 36 + n] = (nn < N) ? g_h[(size_t)nn * 512 + i * 8] : 0.f;
    }
    __syncthreads();

    int ox = (tid & 15) * 4;
    int nl = (tid >> 4) * 2;
    float acc[2][4];
    #pragma unroll
    for (int a = 0; a < 2; a++)
        #pragma unroll
        for (int b = 0; b < 4; b++) acc[a][b] = 0.f;

    #pragma unroll 8
    for (int i = 0; i < 64; i++) {
        float4 w = *(const float4*)&wT[i * 68 + ox];
        float2 a = *(const float2*)&xT[i * 36 + nl];
        acc[0][0] += a.x * w.x; acc[0][1] += a.x * w.y; acc[0][2] += a.x * w.z; acc[0][3] += a.x * w.w;
        acc[1][0] += a.y * w.x; acc[1][1] += a.y * w.y; acc[1][2] += a.y * w.z; acc[1][3] += a.y * w.w;
    }

    #pragma unroll
    for (int jj = 0; jj < 2; jj++) {
        int b = sbt[nl + jj];
        if (b < 0) continue;
        #pragma unroll
        for (int cc = 0; cc < 4; cc++) {
            int o = ox + cc;
            atomicAdd(&g_gsum[b * 64 + o], acc[jj][cc] + sb[o]);
        }
    }
}

__global__ void __launch_bounds__(64) k_post(const float* __restrict__ pw1,
        const float* __restrict__ pb1, const float* __restrict__ pw2,
        const float* __restrict__ pb2, float* __restrict__ out) {
    __shared__ float sg[64];
    __shared__ float sh[64];
    int b = blockIdx.x, tid = threadIdx.x;
    sg[tid] = g_gsum[b * 64 + tid];
    __syncthreads();
    float a = pb1[tid];
    const float* wr = pw1 + tid * 64;
    #pragma unroll 8
    for (int i = 0; i < 64; i++) a += wr[i] * sg[i];
    float s = a * sigmoidf(a);
    sh[tid] = s * pw2[tid];
    __syncthreads();
    for (int st = 32; st; st >>= 1) {
        if (tid < st) sh[tid] += sh[tid + st];
        __syncthreads();
    }
    if (tid == 0) out[b] = sh[0] + pb2[0];
}

// ---------------- launch ----------------
extern "C" void kernel_launch(void* const* d_in, const int* in_sizes, int n_in,
                              void* d_out, int out_size) {
    const float* pos   = (const float*)d_in[0];
    const int*   zi    = (const int*)d_in[1];
    const int*   ei    = (const int*)d_in[2];
    const int*   batch = (const int*)d_in[3];
    const float* atomw = (const float*)d_in[4];
    const float* inw   = (const float*)d_in[5];
    const float* inb   = (const float*)d_in[6];
    const float* ew1   = (const float*)d_in[7];
    const float* eb1   = (const float*)d_in[8];
    const float* ew2   = (const float*)d_in[9];
    const float* eb2   = (const float*)d_in[10];
    const float* projw = (const float*)d_in[11];
    const float* projb = (const float*)d_in[12];
    const float* asrc  = (const float*)d_in[13];
    const float* adst  = (const float*)d_in[14];
    const float* wsrc  = (const float*)d_in[15];
    const float* wdst  = (const float*)d_in[16];
    const float* lna   = (const float*)d_in[17];
    const float* silua = (const float*)d_in[18];
    const float* silub = (const float*)d_in[19];
    const float* ppw   = (const float*)d_in[20];
    const float* ppb   = (const float*)d_in[21];
    const float* pw1   = (const float*)d_in[22];
    const float* pb1   = (const float*)d_in[23];
    const float* pw2   = (const float*)d_in[24];
    const float* pb2   = (const float*)d_in[25];
    float* out = (float*)d_out;

    int N = in_sizes[0] / 3;
    int E = in_sizes[2] / 2;
    const int* src = ei;
    const int* dst = ei + E;
    int G = (N + 1023) / 1024;
    const int MVSMEM = (8704 + 8192) * 4;

    cudaFuncSetAttribute(k_mvlin, cudaFuncAttributeMaxDynamicSharedMemorySize, MVSMEM);

    k_zero<<<64, 256>>>(N);
    k_init<<<(E + 255) / 256, 256>>>(pos, batch, dst, N, E);
    k_embed<<<(N + 31) / 32, 256>>>(zi, batch, pos, atomw, inw, inb, N);
    dim3 mvgrid((N + 31) / 32, 2);
    k_mvlin<<<mvgrid, 256, MVSMEM>>>(projw, projb, asrc, adst, wsrc, wdst, N);
    k_scanA<<<G, 1024>>>(N);
    k_scanB<<<G, 256>>>(N, E, G);
    k_edgefill<<<(E + 127) / 128, 128>>>(pos, src, dst, ew1, eb1, ew2, eb2, E);

    k_attn<<<(N + 3) / 4, 128>>>(silua, silub, lna, N);
    for (int l = 1; l < 4; l++) {
        k_mvlin<<<mvgrid, 256, MVSMEM>>>(projw + (size_t)l * 4 * 64 * 64,
                                         projb + l * 64,
                                         asrc + l * 512, adst + l * 512,
                                         wsrc + l * 16, wdst + l * 16, N);
        k_attn<<<(N + 3) / 4, 128>>>(silua + l * 256, silub + l * 256, lna + l * 64, N);
    }

    k_prepool<<<(N + 31) / 32, 256>>>(ppw, ppb, batch, N);
    k_post<<<NB, 64>>>(pw1, pb1, pw2, pb2, out);
}